// round 1
// baseline (speedup 1.0000x reference)
#include <cuda_runtime.h>
#include <cuda_bf16.h>
#include <math.h>

// Problem constants (from reference setup_inputs)
#define MAX_N 50000
#define MAX_E 800000
#define F_OUT 64

// Scratch (device globals — no allocation allowed)
__device__ float g_z[MAX_N * F_OUT];
__device__ float g_h[MAX_N * F_OUT];
__device__ float g_sd[MAX_N];
__device__ float g_ss[MAX_N];
__device__ int   g_deg[MAX_N];
__device__ int   g_offs[MAX_N + 1];
__device__ int   g_cursor[MAX_N];
__device__ int   g_esrc[MAX_E];

// ---------------------------------------------------------------------------
// GEMM: C[M,64] = relu(A[M,K] @ B[64,K]^T), K in {256, 64}, row-major.
// Tile: BM=128 rows x BN=64 cols, BK=32, 256 threads, 8x4 outputs/thread.
// ---------------------------------------------------------------------------
#define BM 128
#define BN 64
#define BK 32

__device__ __forceinline__ void gemm_relu_body(
    const float* __restrict__ A, const float* __restrict__ B,
    float* __restrict__ C, int M, int K)
{
    __shared__ float As[BM][BK + 1];
    __shared__ float Bs[BN][BK + 1];

    int tid = threadIdx.x;           // 0..255
    int tx = tid & 15;               // col group 0..15
    int ty = tid >> 4;               // row group 0..15
    int row0 = blockIdx.x * BM;

    float acc[8][4];
#pragma unroll
    for (int i = 0; i < 8; i++)
#pragma unroll
        for (int j = 0; j < 4; j++) acc[i][j] = 0.0f;

    for (int kb = 0; kb < K; kb += BK) {
        // Load A tile: 128x32 floats = 1024 float4, 4 per thread
#pragma unroll
        for (int q = 0; q < 4; q++) {
            int idx = tid + q * 256;         // 0..1023
            int r = idx >> 3;                // row in tile
            int k4 = idx & 7;                // float4 within row
            int grow = row0 + r;
            float4 v = make_float4(0.f, 0.f, 0.f, 0.f);
            if (grow < M)
                v = *(const float4*)(A + (size_t)grow * K + kb + k4 * 4);
            As[r][k4 * 4 + 0] = v.x;
            As[r][k4 * 4 + 1] = v.y;
            As[r][k4 * 4 + 2] = v.z;
            As[r][k4 * 4 + 3] = v.w;
        }
        // Load B tile: 64x32 floats = 512 float4, 2 per thread
#pragma unroll
        for (int q = 0; q < 2; q++) {
            int idx = tid + q * 256;         // 0..511
            int r = idx >> 3;
            int k4 = idx & 7;
            float4 v = *(const float4*)(B + (size_t)r * K + kb + k4 * 4);
            Bs[r][k4 * 4 + 0] = v.x;
            Bs[r][k4 * 4 + 1] = v.y;
            Bs[r][k4 * 4 + 2] = v.z;
            Bs[r][k4 * 4 + 3] = v.w;
        }
        __syncthreads();

#pragma unroll
        for (int k = 0; k < BK; k++) {
            float a[8], b[4];
#pragma unroll
            for (int i = 0; i < 8; i++) a[i] = As[ty + i * 16][k];
#pragma unroll
            for (int j = 0; j < 4; j++) b[j] = Bs[tx + j * 16][k];
#pragma unroll
            for (int i = 0; i < 8; i++)
#pragma unroll
                for (int j = 0; j < 4; j++)
                    acc[i][j] = fmaf(a[i], b[j], acc[i][j]);
        }
        __syncthreads();
    }

#pragma unroll
    for (int i = 0; i < 8; i++) {
        int row = row0 + ty + i * 16;
        if (row < M) {
#pragma unroll
            for (int j = 0; j < 4; j++) {
                int col = tx + j * 16;
                float v = acc[i][j];
                C[(size_t)row * 64 + col] = v > 0.f ? v : 0.f;
            }
        }
    }
}

__global__ void gemm1_kernel(const float* __restrict__ x,
                             const float* __restrict__ W1, int N) {
    gemm_relu_body(x, W1, g_z, N, 256);
}

__global__ void gemm2_kernel(const float* __restrict__ W2, int N) {
    gemm_relu_body(g_z, W2, g_h, N, 64);
}

// ---------------------------------------------------------------------------
// Per-node attention dots: sd[i] = h[i]·a[0:64], ss[i] = h[i]·a[64:128]
// One warp per node; coalesced h loads.
// ---------------------------------------------------------------------------
__global__ void dots_kernel(const float* __restrict__ a, int N) {
    int warp = (blockIdx.x * blockDim.x + threadIdx.x) >> 5;
    int lane = threadIdx.x & 31;
    if (warp >= N) return;
    float h0 = g_h[(size_t)warp * 64 + lane];
    float h1 = g_h[(size_t)warp * 64 + 32 + lane];
    float d = fmaf(h1, a[32 + lane], h0 * a[lane]);
    float s = fmaf(h1, a[96 + lane], h0 * a[64 + lane]);
#pragma unroll
    for (int o = 16; o; o >>= 1) {
        d += __shfl_xor_sync(0xFFFFFFFFu, d, o);
        s += __shfl_xor_sync(0xFFFFFFFFu, s, o);
    }
    if (lane == 0) { g_sd[warp] = d; g_ss[warp] = s; }
}

// ---------------------------------------------------------------------------
// CSR build: zero -> histogram -> single-block scan -> scatter
// ---------------------------------------------------------------------------
__global__ void zero_deg_kernel(int N) {
    int i = blockIdx.x * blockDim.x + threadIdx.x;
    if (i < N) g_deg[i] = 0;
}

__global__ void hist_kernel(const int* __restrict__ dst, int E) {
    int i = blockIdx.x * blockDim.x + threadIdx.x;
    if (i < E) atomicAdd(&g_deg[dst[i]], 1);
}

__global__ void scan_kernel(int N) {
    __shared__ int wsum[32];
    __shared__ int carry;
    int tid = threadIdx.x;             // 1024 threads
    int lane = tid & 31, wid = tid >> 5;
    if (tid == 0) carry = 0;
    __syncthreads();
    for (int base = 0; base < N; base += 1024) {
        int i = base + tid;
        int v = (i < N) ? g_deg[i] : 0;
        // warp inclusive scan
        int x = v;
#pragma unroll
        for (int o = 1; o < 32; o <<= 1) {
            int t = __shfl_up_sync(0xFFFFFFFFu, x, o);
            if (lane >= o) x += t;
        }
        if (lane == 31) wsum[wid] = x;
        __syncthreads();
        if (wid == 0) {
            int y = wsum[lane];
#pragma unroll
            for (int o = 1; o < 32; o <<= 1) {
                int t = __shfl_up_sync(0xFFFFFFFFu, y, o);
                if (lane >= o) y += t;
            }
            wsum[lane] = y;
        }
        __syncthreads();
        int warp_prefix = (wid > 0) ? wsum[wid - 1] : 0;
        int incl = x + warp_prefix;
        int excl = incl - v + carry;
        if (i < N) { g_offs[i] = excl; g_cursor[i] = excl; }
        __syncthreads();
        if (tid == 1023) carry += wsum[31];
        __syncthreads();
    }
    if (tid == 0) g_offs[N] = carry;
}

__global__ void scatter_kernel(const int* __restrict__ src,
                               const int* __restrict__ dst, int E) {
    int i = blockIdx.x * blockDim.x + threadIdx.x;
    if (i < E) {
        int p = atomicAdd(&g_cursor[dst[i]], 1);
        g_esrc[p] = src[i];
    }
}

// ---------------------------------------------------------------------------
// Aggregate: one warp per destination node. Two passes over the node's edges:
//   pass 1: segment max of leaky_relu(sd[dst] + ss[src])
//   pass 2: e = exp(score - m); esum += e; acc += e * h[src]
// Then out[dst] = relu(h[dst] - acc/esum). No atomics.
// ---------------------------------------------------------------------------
__global__ void aggregate_kernel(float* __restrict__ out, int N) {
    int warp = (blockIdx.x * blockDim.x + threadIdx.x) >> 5;
    int lane = threadIdx.x & 31;
    if (warp >= N) return;
    int dst = warp;
    int beg = g_offs[dst], end = g_offs[dst + 1];
    float sdv = g_sd[dst];

    // pass 1: max (lanes stride over edges)
    float m = -INFINITY;
    for (int j = beg + lane; j < end; j += 32) {
        float sc = sdv + g_ss[g_esrc[j]];
        sc = (sc >= 0.f) ? sc : 0.01f * sc;
        m = fmaxf(m, sc);
    }
#pragma unroll
    for (int o = 16; o; o >>= 1)
        m = fmaxf(m, __shfl_xor_sync(0xFFFFFFFFu, m, o));

    // pass 2: all lanes cooperate per edge (coalesced h row loads)
    float acc0 = 0.f, acc1 = 0.f, esum = 0.f;
    for (int j = beg; j < end; ++j) {
        int s = g_esrc[j];
        float sc = sdv + g_ss[s];
        sc = (sc >= 0.f) ? sc : 0.01f * sc;
        float e = __expf(sc - m);
        esum += e;
        acc0 = fmaf(e, g_h[(size_t)s * 64 + lane], acc0);
        acc1 = fmaf(e, g_h[(size_t)s * 64 + 32 + lane], acc1);
    }
    float inv = (end > beg) ? (1.0f / esum) : 0.0f;
    float h0 = g_h[(size_t)dst * 64 + lane];
    float h1 = g_h[(size_t)dst * 64 + 32 + lane];
    float o0 = h0 - acc0 * inv;
    float o1 = h1 - acc1 * inv;
    out[(size_t)dst * 64 + lane]      = o0 > 0.f ? o0 : 0.f;
    out[(size_t)dst * 64 + 32 + lane] = o1 > 0.f ? o1 : 0.f;
}

// ---------------------------------------------------------------------------
extern "C" void kernel_launch(void* const* d_in, const int* in_sizes, int n_in,
                              void* d_out, int out_size)
{
    const float* x   = (const float*)d_in[0];   // [N, 256]
    const float* W1  = (const float*)d_in[1];   // [64, 256]
    const float* W2  = (const float*)d_in[2];   // [64, 64]
    const float* a   = (const float*)d_in[3];   // [128, 1]
    const int*   src = (const int*)d_in[4];     // [E]
    const int*   dst = (const int*)d_in[5];     // [E]
    float* out = (float*)d_out;

    int N = in_sizes[0] / 256;
    int E = in_sizes[4];

    int gemm_blocks = (N + BM - 1) / BM;
    gemm1_kernel<<<gemm_blocks, 256>>>(x, W1, N);
    gemm2_kernel<<<gemm_blocks, 256>>>(W2, N);

    dots_kernel<<<(N * 32 + 255) / 256, 256>>>(a, N);

    zero_deg_kernel<<<(N + 255) / 256, 256>>>(N);
    hist_kernel<<<(E + 255) / 256, 256>>>(dst, E);
    scan_kernel<<<1, 1024>>>(N);
    scatter_kernel<<<(E + 255) / 256, 256>>>(src, dst, E);

    aggregate_kernel<<<(N * 32 + 255) / 256, 256>>>(out, N);
}

// round 2
// speedup vs baseline: 1.1201x; 1.1201x over previous
#include <cuda_runtime.h>
#include <cuda_bf16.h>
#include <math.h>

#define MAX_N 50000
#define MAX_E 800000

// Scratch (device globals — no allocation allowed)
__device__ float g_h[MAX_N * 64];
__device__ float g_sd[MAX_N];
__device__ float g_ss[MAX_N];
__device__ int   g_deg[MAX_N];
__device__ int   g_offs[MAX_N + 1];
__device__ int   g_cursor[MAX_N];
__device__ int   g_esrc[MAX_E];

// ---------------------------------------------------------------------------
// f32x2 packed-math helpers (sm_103a)
// ---------------------------------------------------------------------------
__device__ __forceinline__ unsigned long long pack2(float x, float y) {
    unsigned long long r;
    asm("mov.b64 %0, {%1, %2};" : "=l"(r) : "f"(x), "f"(y));
    return r;
}
__device__ __forceinline__ float2 unpack2(unsigned long long v) {
    float2 f;
    asm("mov.b64 {%0, %1}, %2;" : "=f"(f.x), "=f"(f.y) : "l"(v));
    return f;
}
__device__ __forceinline__ void fma2(unsigned long long& d,
                                     unsigned long long a,
                                     unsigned long long b) {
    asm("fma.rn.f32x2 %0, %1, %2, %0;" : "+l"(d) : "l"(a), "l"(b));
}

// ---------------------------------------------------------------------------
// Fused MLP: h = relu(relu(x@W1^T)@W2^T), plus per-row dots sd=h·a_dst,
// ss=h·a_src, plus zeroing g_deg. One block = 128 rows, 256 threads.
// Thread tile: 8 rows (as 4 f32x2 pairs) x 4 cols.
// Dynamic smem layout (floats):
//   As   [32][132] @ 0      (phase A x tile, k-major, padded)
//   Bs   [32][64]  @ 4224   (phase A W1 tile, k-major)
//   W2s  [64][68]  @ 0      (phase B, unions with As/Bs region)
//   zs   [64][132] @ 6272   (z tile, k-major = z-col major)
// ---------------------------------------------------------------------------
#define AS_OFF 0
#define BS_OFF 4224
#define W2_OFF 0
#define ZS_OFF 6272
#define SMEM_FLOATS (ZS_OFF + 64 * 132)   // 14720 floats = 58880 B

__global__ __launch_bounds__(256, 2)
void fused_mlp_kernel(const float* __restrict__ x,
                      const float* __restrict__ W1,
                      const float* __restrict__ W2,
                      const float* __restrict__ a,
                      int N)
{
    extern __shared__ float smem[];
    float* As  = smem + AS_OFF;
    float* Bs  = smem + BS_OFF;
    float* W2s = smem + W2_OFF;
    float* zs  = smem + ZS_OFF;

    const int tid  = threadIdx.x;
    const int tx   = tid & 15;       // col group 0..15 -> cols tx*4..+3
    const int ty   = tid >> 4;       // row group 0..15 -> rows ty*8..+7
    const int row0 = blockIdx.x * 128;

    // zero g_deg (independent side job)
    if (tid < 128) {
        int i = row0 + tid;
        if (i < N) g_deg[i] = 0;
    }

    // attention vector slices for this thread's columns
    float a_d[4], a_s[4];
#pragma unroll
    for (int j = 0; j < 4; j++) {
        a_d[j] = a[tx * 4 + j];
        a_s[j] = a[64 + tx * 4 + j];
    }

    // ------------------ Phase A: z = relu(x @ W1^T), K=256 ------------------
    unsigned long long acc[4][4];
#pragma unroll
    for (int p = 0; p < 4; p++)
#pragma unroll
        for (int j = 0; j < 4; j++) acc[p][j] = 0ULL;

    for (int kb = 0; kb < 256; kb += 32) {
        // load x tile -> As[k][r] (k-major, pad 132)
#pragma unroll
        for (int q = 0; q < 4; q++) {
            int idx = tid + q * 256;      // 0..1023
            int r   = idx >> 3;
            int k4  = idx & 7;
            int grow = row0 + r;
            float4 v = make_float4(0.f, 0.f, 0.f, 0.f);
            if (grow < N)
                v = *(const float4*)(x + (size_t)grow * 256 + kb + k4 * 4);
            As[(k4 * 4 + 0) * 132 + r] = v.x;
            As[(k4 * 4 + 1) * 132 + r] = v.y;
            As[(k4 * 4 + 2) * 132 + r] = v.z;
            As[(k4 * 4 + 3) * 132 + r] = v.w;
        }
        // load W1 tile -> Bs[k][c]
#pragma unroll
        for (int q = 0; q < 2; q++) {
            int idx = tid + q * 256;      // 0..511
            int c   = idx >> 3;
            int k4  = idx & 7;
            float4 w = *(const float4*)(W1 + (size_t)c * 256 + kb + k4 * 4);
            Bs[(k4 * 4 + 0) * 64 + c] = w.x;
            Bs[(k4 * 4 + 1) * 64 + c] = w.y;
            Bs[(k4 * 4 + 2) * 64 + c] = w.z;
            Bs[(k4 * 4 + 3) * 64 + c] = w.w;
        }
        __syncthreads();

#pragma unroll 8
        for (int k = 0; k < 32; k++) {
            ulonglong2 av0 = *(const ulonglong2*)(As + k * 132 + ty * 8);
            ulonglong2 av1 = *(const ulonglong2*)(As + k * 132 + ty * 8 + 4);
            float4 bv = *(const float4*)(Bs + k * 64 + tx * 4);
            unsigned long long ap[4] = {av0.x, av0.y, av1.x, av1.y};
            unsigned long long bp[4] = {pack2(bv.x, bv.x), pack2(bv.y, bv.y),
                                        pack2(bv.z, bv.z), pack2(bv.w, bv.w)};
#pragma unroll
            for (int p = 0; p < 4; p++)
#pragma unroll
                for (int j = 0; j < 4; j++)
                    fma2(acc[p][j], ap[p], bp[j]);
        }
        __syncthreads();
    }

    // relu + write z tile k-major: zs[col][row]; load W2 into (freed) As region
#pragma unroll
    for (int p = 0; p < 4; p++)
#pragma unroll
        for (int j = 0; j < 4; j++) {
            float2 f = unpack2(acc[p][j]);
            f.x = f.x > 0.f ? f.x : 0.f;
            f.y = f.y > 0.f ? f.y : 0.f;
            int rl = ty * 8 + p * 2;
            int c  = tx * 4 + j;
            zs[c * 132 + rl]     = f.x;
            zs[c * 132 + rl + 1] = f.y;
        }
#pragma unroll
    for (int q = 0; q < 16; q++) {
        int idx = tid + q * 256;          // 0..4095, idx = c*64 + k
        int c = idx >> 6;
        int k = idx & 63;
        W2s[k * 68 + c] = W2[idx];
    }
    __syncthreads();

    // ------------------ Phase B: h = relu(z @ W2^T), K=64 -------------------
    unsigned long long hacc[4][4];
#pragma unroll
    for (int p = 0; p < 4; p++)
#pragma unroll
        for (int j = 0; j < 4; j++) hacc[p][j] = 0ULL;

#pragma unroll 8
    for (int k = 0; k < 64; k++) {
        ulonglong2 av0 = *(const ulonglong2*)(zs + k * 132 + ty * 8);
        ulonglong2 av1 = *(const ulonglong2*)(zs + k * 132 + ty * 8 + 4);
        float4 bv = *(const float4*)(W2s + k * 68 + tx * 4);
        unsigned long long ap[4] = {av0.x, av0.y, av1.x, av1.y};
        unsigned long long bp[4] = {pack2(bv.x, bv.x), pack2(bv.y, bv.y),
                                    pack2(bv.z, bv.z), pack2(bv.w, bv.w)};
#pragma unroll
        for (int p = 0; p < 4; p++)
#pragma unroll
            for (int j = 0; j < 4; j++)
                fma2(hacc[p][j], ap[p], bp[j]);
    }

    // ------------------ Epilogue: relu, store h, dots -----------------------
    float hv[4][4][2];   // [pair][col][q]
    float pd[8], ps[8];
#pragma unroll
    for (int r = 0; r < 8; r++) { pd[r] = 0.f; ps[r] = 0.f; }

#pragma unroll
    for (int p = 0; p < 4; p++)
#pragma unroll
        for (int j = 0; j < 4; j++) {
            float2 f = unpack2(hacc[p][j]);
            f.x = f.x > 0.f ? f.x : 0.f;
            f.y = f.y > 0.f ? f.y : 0.f;
            hv[p][j][0] = f.x;
            hv[p][j][1] = f.y;
            pd[p * 2 + 0] = fmaf(f.x, a_d[j], pd[p * 2 + 0]);
            pd[p * 2 + 1] = fmaf(f.y, a_d[j], pd[p * 2 + 1]);
            ps[p * 2 + 0] = fmaf(f.x, a_s[j], ps[p * 2 + 0]);
            ps[p * 2 + 1] = fmaf(f.y, a_s[j], ps[p * 2 + 1]);
        }

    // store h rows (float4 per row)
#pragma unroll
    for (int p = 0; p < 4; p++)
#pragma unroll
        for (int q = 0; q < 2; q++) {
            int row = row0 + ty * 8 + p * 2 + q;
            if (row < N) {
                float4 o = make_float4(hv[p][0][q], hv[p][1][q],
                                       hv[p][2][q], hv[p][3][q]);
                *(float4*)(g_h + (size_t)row * 64 + tx * 4) = o;
            }
        }

    // reduce dots across tx (16 lanes within each half-warp)
#pragma unroll
    for (int off = 8; off; off >>= 1)
#pragma unroll
        for (int r = 0; r < 8; r++) {
            pd[r] += __shfl_xor_sync(0xFFFFFFFFu, pd[r], off);
            ps[r] += __shfl_xor_sync(0xFFFFFFFFu, ps[r], off);
        }
    if (tx == 0) {
#pragma unroll
        for (int r = 0; r < 8; r++) {
            int row = row0 + ty * 8 + r;
            if (row < N) { g_sd[row] = pd[r]; g_ss[row] = ps[r]; }
        }
    }
}

// ---------------------------------------------------------------------------
// CSR build
// ---------------------------------------------------------------------------
__global__ void hist_kernel(const int* __restrict__ dst, int E) {
    int i = blockIdx.x * blockDim.x + threadIdx.x;
    if (i < E) atomicAdd(&g_deg[dst[i]], 1);
}

__global__ void scan_kernel(int N) {
    __shared__ int wsum[32];
    __shared__ int carry_s;
    int tid = threadIdx.x, lane = tid & 31, wid = tid >> 5;
    if (tid == 0) carry_s = 0;
    __syncthreads();
    for (int base = 0; base < N; base += 4096) {
        int i = base + tid * 4;
        int v0 = 0, v1 = 0, v2 = 0, v3 = 0;
        if (i + 3 < N) {
            int4 t = *(const int4*)&g_deg[i];
            v0 = t.x; v1 = t.y; v2 = t.z; v3 = t.w;
        } else {
            if (i     < N) v0 = g_deg[i];
            if (i + 1 < N) v1 = g_deg[i + 1];
            if (i + 2 < N) v2 = g_deg[i + 2];
        }
        int s = v0 + v1 + v2 + v3;
        int xi = s;
#pragma unroll
        for (int o = 1; o < 32; o <<= 1) {
            int t = __shfl_up_sync(0xFFFFFFFFu, xi, o);
            if (lane >= o) xi += t;
        }
        if (lane == 31) wsum[wid] = xi;
        __syncthreads();
        if (wid == 0) {
            int y = wsum[lane];
#pragma unroll
            for (int o = 1; o < 32; o <<= 1) {
                int t = __shfl_up_sync(0xFFFFFFFFu, y, o);
                if (lane >= o) y += t;
            }
            wsum[lane] = y;
        }
        __syncthreads();
        int excl = xi - s + (wid ? wsum[wid - 1] : 0) + carry_s;
        int o0 = excl, o1 = o0 + v0, o2 = o1 + v1, o3 = o2 + v2;
        if (i     < N) { g_offs[i]     = o0; g_cursor[i]     = o0; }
        if (i + 1 < N) { g_offs[i + 1] = o1; g_cursor[i + 1] = o1; }
        if (i + 2 < N) { g_offs[i + 2] = o2; g_cursor[i + 2] = o2; }
        if (i + 3 < N) { g_offs[i + 3] = o3; g_cursor[i + 3] = o3; }
        __syncthreads();
        if (tid == 0) carry_s += wsum[31];
        __syncthreads();
    }
    if (tid == 0) g_offs[N] = carry_s;
}

__global__ void scatter_kernel(const int* __restrict__ src,
                               const int* __restrict__ dst, int E) {
    int i = blockIdx.x * blockDim.x + threadIdx.x;
    if (i < E) {
        int p = atomicAdd(&g_cursor[dst[i]], 1);
        g_esrc[p] = src[i];
    }
}

// ---------------------------------------------------------------------------
// Aggregate: one warp per destination. Pass 1 max, pass 2 exp/sum + weighted
// accumulation (float2 lanes + fma2). out = relu(h - acc/esum).
// ---------------------------------------------------------------------------
__global__ void aggregate_kernel(float* __restrict__ out, int N) {
    int warp = (blockIdx.x * blockDim.x + threadIdx.x) >> 5;
    int lane = threadIdx.x & 31;
    if (warp >= N) return;
    int dst = warp;
    int beg = g_offs[dst], end = g_offs[dst + 1];
    float sdv = g_sd[dst];

    float m = -INFINITY;
    for (int j = beg + lane; j < end; j += 32) {
        float sc = sdv + g_ss[g_esrc[j]];
        sc = (sc >= 0.f) ? sc : 0.01f * sc;
        m = fmaxf(m, sc);
    }
#pragma unroll
    for (int o = 16; o; o >>= 1)
        m = fmaxf(m, __shfl_xor_sync(0xFFFFFFFFu, m, o));

    const float2* hb = (const float2*)g_h;
    unsigned long long acc = 0ULL;
    float esum = 0.f;
    for (int j = beg; j < end; ++j) {
        int s = g_esrc[j];
        float sc = sdv + g_ss[s];
        sc = (sc >= 0.f) ? sc : 0.01f * sc;
        float e = __expf(sc - m);
        esum += e;
        float2 hvv = hb[(size_t)s * 32 + lane];
        fma2(acc, *(unsigned long long*)&hvv, pack2(e, e));
    }
    float inv = (end > beg) ? (1.0f / esum) : 0.0f;
    float2 hd = hb[(size_t)dst * 32 + lane];
    float2 af = unpack2(acc);
    float2 o;
    o.x = hd.x - af.x * inv;
    o.y = hd.y - af.y * inv;
    o.x = o.x > 0.f ? o.x : 0.f;
    o.y = o.y > 0.f ? o.y : 0.f;
    ((float2*)out)[(size_t)dst * 32 + lane] = o;
}

// ---------------------------------------------------------------------------
extern "C" void kernel_launch(void* const* d_in, const int* in_sizes, int n_in,
                              void* d_out, int out_size)
{
    const float* x   = (const float*)d_in[0];   // [N, 256]
    const float* W1  = (const float*)d_in[1];   // [64, 256]
    const float* W2  = (const float*)d_in[2];   // [64, 64]
    const float* a   = (const float*)d_in[3];   // [128, 1]
    const int*   src = (const int*)d_in[4];     // [E]
    const int*   dst = (const int*)d_in[5];     // [E]
    float* out = (float*)d_out;

    int N = in_sizes[0] / 256;
    int E = in_sizes[4];

    static_assert(SMEM_FLOATS * 4 == 58880, "smem layout");
    cudaFuncSetAttribute(fused_mlp_kernel,
                         cudaFuncAttributeMaxDynamicSharedMemorySize,
                         SMEM_FLOATS * 4);

    int blocks = (N + 127) / 128;
    fused_mlp_kernel<<<blocks, 256, SMEM_FLOATS * 4>>>(x, W1, W2, a, N);

    hist_kernel<<<(E + 255) / 256, 256>>>(dst, E);
    scan_kernel<<<1, 1024>>>(N);
    scatter_kernel<<<(E + 255) / 256, 256>>>(src, dst, E);
    aggregate_kernel<<<(N * 32 + 255) / 256, 256>>>(out, N);
}

// round 3
// speedup vs baseline: 1.1473x; 1.0243x over previous
#include <cuda_runtime.h>
#include <cuda_bf16.h>
#include <math.h>

#define MAX_N 50000
#define MAX_E 800000
#define HIST_BLOCKS 128

// Scratch (device globals — no allocation allowed; zero-initialized at load)
__device__ float g_h[MAX_N * 64];
__device__ float g_sd[MAX_N];
__device__ float g_ss[MAX_N];
__device__ int   g_deg[MAX_N];          // zeroed by scan_kernel for next call
__device__ int   g_offs[MAX_N + 1];
__device__ int   g_cursor[MAX_N];
__device__ int   g_esrc[MAX_E];
__device__ float g_escore[MAX_E];

// ---------------------------------------------------------------------------
// f32x2 packed-math helpers (sm_103a)
// ---------------------------------------------------------------------------
__device__ __forceinline__ unsigned long long pack2(float x, float y) {
    unsigned long long r;
    asm("mov.b64 %0, {%1, %2};" : "=l"(r) : "f"(x), "f"(y));
    return r;
}
__device__ __forceinline__ float2 unpack2(unsigned long long v) {
    float2 f;
    asm("mov.b64 {%0, %1}, %2;" : "=f"(f.x), "=f"(f.y) : "l"(v));
    return f;
}
__device__ __forceinline__ void fma2(unsigned long long& d,
                                     unsigned long long a,
                                     unsigned long long b) {
    asm("fma.rn.f32x2 %0, %1, %2, %0;" : "+l"(d) : "l"(a), "l"(b));
}

// ---------------------------------------------------------------------------
// Fused kernel. Blocks [0, HIST_BLOCKS): degree histogram (g_deg assumed
// pre-zeroed — by module load on call 1, by scan_kernel thereafter).
// Blocks [HIST_BLOCKS, ...): MLP h = relu(relu(x@W1^T)@W2^T) for 128 rows,
// + per-row dots sd = h·a[0:64], ss = h·a[64:128].
// Dynamic smem layout (floats):
//   As  [32][132] @ 0      Bs [32][64] @ 4224   (phase A)
//   W2s [64][68]  @ 0      (phase B, reuses As/Bs)
//   zs  [64][132] @ 6272
// ---------------------------------------------------------------------------
#define AS_OFF 0
#define BS_OFF 4224
#define W2_OFF 0
#define ZS_OFF 6272
#define SMEM_FLOATS (ZS_OFF + 64 * 132)   // 14720 floats = 58880 B

__global__ __launch_bounds__(256, 2)
void fused_mlp_hist_kernel(const float* __restrict__ x,
                           const float* __restrict__ W1,
                           const float* __restrict__ W2,
                           const float* __restrict__ a,
                           const int* __restrict__ dst,
                           int N, int E)
{
    const int tid = threadIdx.x;

    // ---- hist role ----
    if (blockIdx.x < HIST_BLOCKS) {
        int stride = HIST_BLOCKS * 256;
        for (int i = blockIdx.x * 256 + tid; i < E; i += stride)
            atomicAdd(&g_deg[dst[i]], 1);
        return;
    }

    // ---- MLP role ----
    extern __shared__ float smem[];
    float* As  = smem + AS_OFF;
    float* Bs  = smem + BS_OFF;
    float* W2s = smem + W2_OFF;
    float* zs  = smem + ZS_OFF;

    const int tx   = tid & 15;
    const int ty   = tid >> 4;
    const int row0 = (blockIdx.x - HIST_BLOCKS) * 128;

    float a_d[4], a_s[4];
#pragma unroll
    for (int j = 0; j < 4; j++) {
        a_d[j] = a[tx * 4 + j];
        a_s[j] = a[64 + tx * 4 + j];
    }

    // ------------------ Phase A: z = relu(x @ W1^T), K=256 ------------------
    unsigned long long acc[4][4];
#pragma unroll
    for (int p = 0; p < 4; p++)
#pragma unroll
        for (int j = 0; j < 4; j++) acc[p][j] = 0ULL;

    for (int kb = 0; kb < 256; kb += 32) {
#pragma unroll
        for (int q = 0; q < 4; q++) {
            int idx = tid + q * 256;
            int r   = idx >> 3;
            int k4  = idx & 7;
            int grow = row0 + r;
            float4 v = make_float4(0.f, 0.f, 0.f, 0.f);
            if (grow < N)
                v = *(const float4*)(x + (size_t)grow * 256 + kb + k4 * 4);
            As[(k4 * 4 + 0) * 132 + r] = v.x;
            As[(k4 * 4 + 1) * 132 + r] = v.y;
            As[(k4 * 4 + 2) * 132 + r] = v.z;
            As[(k4 * 4 + 3) * 132 + r] = v.w;
        }
#pragma unroll
        for (int q = 0; q < 2; q++) {
            int idx = tid + q * 256;
            int c   = idx >> 3;
            int k4  = idx & 7;
            float4 w = *(const float4*)(W1 + (size_t)c * 256 + kb + k4 * 4);
            Bs[(k4 * 4 + 0) * 64 + c] = w.x;
            Bs[(k4 * 4 + 1) * 64 + c] = w.y;
            Bs[(k4 * 4 + 2) * 64 + c] = w.z;
            Bs[(k4 * 4 + 3) * 64 + c] = w.w;
        }
        __syncthreads();

#pragma unroll 8
        for (int k = 0; k < 32; k++) {
            ulonglong2 av0 = *(const ulonglong2*)(As + k * 132 + ty * 8);
            ulonglong2 av1 = *(const ulonglong2*)(As + k * 132 + ty * 8 + 4);
            float4 bv = *(const float4*)(Bs + k * 64 + tx * 4);
            unsigned long long ap[4] = {av0.x, av0.y, av1.x, av1.y};
            unsigned long long bp[4] = {pack2(bv.x, bv.x), pack2(bv.y, bv.y),
                                        pack2(bv.z, bv.z), pack2(bv.w, bv.w)};
#pragma unroll
            for (int p = 0; p < 4; p++)
#pragma unroll
                for (int j = 0; j < 4; j++)
                    fma2(acc[p][j], ap[p], bp[j]);
        }
        __syncthreads();
    }

    // relu z -> zs (k-major), load W2 into freed region
#pragma unroll
    for (int p = 0; p < 4; p++)
#pragma unroll
        for (int j = 0; j < 4; j++) {
            float2 f = unpack2(acc[p][j]);
            f.x = f.x > 0.f ? f.x : 0.f;
            f.y = f.y > 0.f ? f.y : 0.f;
            int rl = ty * 8 + p * 2;
            int c  = tx * 4 + j;
            zs[c * 132 + rl]     = f.x;
            zs[c * 132 + rl + 1] = f.y;
        }
#pragma unroll
    for (int q = 0; q < 16; q++) {
        int idx = tid + q * 256;
        int c = idx >> 6;
        int k = idx & 63;
        W2s[k * 68 + c] = W2[idx];
    }
    __syncthreads();

    // ------------------ Phase B: h = relu(z @ W2^T), K=64 -------------------
    unsigned long long hacc[4][4];
#pragma unroll
    for (int p = 0; p < 4; p++)
#pragma unroll
        for (int j = 0; j < 4; j++) hacc[p][j] = 0ULL;

#pragma unroll 8
    for (int k = 0; k < 64; k++) {
        ulonglong2 av0 = *(const ulonglong2*)(zs + k * 132 + ty * 8);
        ulonglong2 av1 = *(const ulonglong2*)(zs + k * 132 + ty * 8 + 4);
        float4 bv = *(const float4*)(W2s + k * 68 + tx * 4);
        unsigned long long ap[4] = {av0.x, av0.y, av1.x, av1.y};
        unsigned long long bp[4] = {pack2(bv.x, bv.x), pack2(bv.y, bv.y),
                                    pack2(bv.z, bv.z), pack2(bv.w, bv.w)};
#pragma unroll
        for (int p = 0; p < 4; p++)
#pragma unroll
            for (int j = 0; j < 4; j++)
                fma2(hacc[p][j], ap[p], bp[j]);
    }

    // ------------------ Epilogue: relu, store h, dots -----------------------
    float hv[4][4][2];
    float pd[8], ps[8];
#pragma unroll
    for (int r = 0; r < 8; r++) { pd[r] = 0.f; ps[r] = 0.f; }

#pragma unroll
    for (int p = 0; p < 4; p++)
#pragma unroll
        for (int j = 0; j < 4; j++) {
            float2 f = unpack2(hacc[p][j]);
            f.x = f.x > 0.f ? f.x : 0.f;
            f.y = f.y > 0.f ? f.y : 0.f;
            hv[p][j][0] = f.x;
            hv[p][j][1] = f.y;
            pd[p * 2 + 0] = fmaf(f.x, a_d[j], pd[p * 2 + 0]);
            pd[p * 2 + 1] = fmaf(f.y, a_d[j], pd[p * 2 + 1]);
            ps[p * 2 + 0] = fmaf(f.x, a_s[j], ps[p * 2 + 0]);
            ps[p * 2 + 1] = fmaf(f.y, a_s[j], ps[p * 2 + 1]);
        }

#pragma unroll
    for (int p = 0; p < 4; p++)
#pragma unroll
        for (int q = 0; q < 2; q++) {
            int row = row0 + ty * 8 + p * 2 + q;
            if (row < N) {
                float4 o = make_float4(hv[p][0][q], hv[p][1][q],
                                       hv[p][2][q], hv[p][3][q]);
                *(float4*)(g_h + (size_t)row * 64 + tx * 4) = o;
            }
        }

#pragma unroll
    for (int off = 8; off; off >>= 1)
#pragma unroll
        for (int r = 0; r < 8; r++) {
            pd[r] += __shfl_xor_sync(0xFFFFFFFFu, pd[r], off);
            ps[r] += __shfl_xor_sync(0xFFFFFFFFu, ps[r], off);
        }
    if (tx == 0) {
#pragma unroll
        for (int r = 0; r < 8; r++) {
            int row = row0 + ty * 8 + r;
            if (row < N) { g_sd[row] = pd[r]; g_ss[row] = ps[r]; }
        }
    }
}

// ---------------------------------------------------------------------------
// Scan: exclusive prefix of g_deg -> g_offs/g_cursor, and ZERO g_deg for the
// next invocation (first invocation relies on zero-initialized globals).
// ---------------------------------------------------------------------------
__global__ void scan_kernel(int N) {
    __shared__ int wsum[32];
    __shared__ int carry_s;
    int tid = threadIdx.x, lane = tid & 31, wid = tid >> 5;
    if (tid == 0) carry_s = 0;
    __syncthreads();
    for (int base = 0; base < N; base += 4096) {
        int i = base + tid * 4;
        int v0 = 0, v1 = 0, v2 = 0, v3 = 0;
        if (i + 3 < N) {
            int4 t = *(const int4*)&g_deg[i];
            v0 = t.x; v1 = t.y; v2 = t.z; v3 = t.w;
            *(int4*)&g_deg[i] = make_int4(0, 0, 0, 0);
        } else {
            if (i     < N) { v0 = g_deg[i];     g_deg[i]     = 0; }
            if (i + 1 < N) { v1 = g_deg[i + 1]; g_deg[i + 1] = 0; }
            if (i + 2 < N) { v2 = g_deg[i + 2]; g_deg[i + 2] = 0; }
        }
        int s = v0 + v1 + v2 + v3;
        int xi = s;
#pragma unroll
        for (int o = 1; o < 32; o <<= 1) {
            int t = __shfl_up_sync(0xFFFFFFFFu, xi, o);
            if (lane >= o) xi += t;
        }
        if (lane == 31) wsum[wid] = xi;
        __syncthreads();
        if (wid == 0) {
            int y = wsum[lane];
#pragma unroll
            for (int o = 1; o < 32; o <<= 1) {
                int t = __shfl_up_sync(0xFFFFFFFFu, y, o);
                if (lane >= o) y += t;
            }
            wsum[lane] = y;
        }
        __syncthreads();
        int excl = xi - s + (wid ? wsum[wid - 1] : 0) + carry_s;
        int o0 = excl, o1 = o0 + v0, o2 = o1 + v1, o3 = o2 + v2;
        if (i     < N) { g_offs[i]     = o0; g_cursor[i]     = o0; }
        if (i + 1 < N) { g_offs[i + 1] = o1; g_cursor[i + 1] = o1; }
        if (i + 2 < N) { g_offs[i + 2] = o2; g_cursor[i + 2] = o2; }
        if (i + 3 < N) { g_offs[i + 3] = o3; g_cursor[i + 3] = o3; }
        __syncthreads();
        if (tid == 0) carry_s += wsum[31];
        __syncthreads();
    }
    if (tid == 0) g_offs[N] = carry_s;
}

__global__ void scatter_kernel(const int* __restrict__ src,
                               const int* __restrict__ dst, int E) {
    int i = blockIdx.x * blockDim.x + threadIdx.x;
    if (i < E) {
        int p = atomicAdd(&g_cursor[dst[i]], 1);
        g_esrc[p] = src[i];
    }
}

// ---------------------------------------------------------------------------
// Aggregate: one warp per destination.
// Pass 1: lanes stride edges; gather ss[src] ONCE, compute leaky score, stash
//         to contiguous g_escore, track max.
// Pass 2: uniform loop over edges (scores re-read as broadcast), exp/sum +
//         float2/fma2 weighted accumulation of h rows, 2x unrolled.
// out = relu(h - acc/esum).
// ---------------------------------------------------------------------------
__global__ void aggregate_kernel(float* __restrict__ out, int N) {
    int warp = (blockIdx.x * blockDim.x + threadIdx.x) >> 5;
    int lane = threadIdx.x & 31;
    if (warp >= N) return;
    int beg = g_offs[warp], end = g_offs[warp + 1];
    float sdv = g_sd[warp];

    float m = -INFINITY;
    for (int j = beg + lane; j < end; j += 32) {
        float sc = sdv + g_ss[g_esrc[j]];
        sc = (sc >= 0.f) ? sc : 0.01f * sc;
        g_escore[j] = sc;
        m = fmaxf(m, sc);
    }
#pragma unroll
    for (int o = 16; o; o >>= 1)
        m = fmaxf(m, __shfl_xor_sync(0xFFFFFFFFu, m, o));
    __syncwarp();

    const float2* hb = (const float2*)g_h;
    unsigned long long acc = 0ULL;
    float esum = 0.f;
    int j = beg;
    for (; j + 2 <= end; j += 2) {
        int   s0 = g_esrc[j],     s1 = g_esrc[j + 1];
        float c0 = g_escore[j],   c1 = g_escore[j + 1];
        float e0 = __expf(c0 - m), e1 = __expf(c1 - m);
        esum += e0 + e1;
        float2 h0 = hb[(size_t)s0 * 32 + lane];
        float2 h1 = hb[(size_t)s1 * 32 + lane];
        fma2(acc, *(unsigned long long*)&h0, pack2(e0, e0));
        fma2(acc, *(unsigned long long*)&h1, pack2(e1, e1));
    }
    if (j < end) {
        int   s0 = g_esrc[j];
        float e0 = __expf(g_escore[j] - m);
        esum += e0;
        float2 h0 = hb[(size_t)s0 * 32 + lane];
        fma2(acc, *(unsigned long long*)&h0, pack2(e0, e0));
    }

    float inv = (end > beg) ? (1.0f / esum) : 0.0f;
    float2 hd = hb[(size_t)warp * 32 + lane];
    float2 af = unpack2(acc);
    float2 o;
    o.x = hd.x - af.x * inv;
    o.y = hd.y - af.y * inv;
    o.x = o.x > 0.f ? o.x : 0.f;
    o.y = o.y > 0.f ? o.y : 0.f;
    ((float2*)out)[(size_t)warp * 32 + lane] = o;
}

// ---------------------------------------------------------------------------
extern "C" void kernel_launch(void* const* d_in, const int* in_sizes, int n_in,
                              void* d_out, int out_size)
{
    const float* x   = (const float*)d_in[0];   // [N, 256]
    const float* W1  = (const float*)d_in[1];   // [64, 256]
    const float* W2  = (const float*)d_in[2];   // [64, 64]
    const float* a   = (const float*)d_in[3];   // [128, 1]
    const int*   src = (const int*)d_in[4];     // [E]
    const int*   dst = (const int*)d_in[5];     // [E]
    float* out = (float*)d_out;

    int N = in_sizes[0] / 256;
    int E = in_sizes[4];

    cudaFuncSetAttribute(fused_mlp_hist_kernel,
                         cudaFuncAttributeMaxDynamicSharedMemorySize,
                         SMEM_FLOATS * 4);

    int mlp_blocks = (N + 127) / 128;
    fused_mlp_hist_kernel<<<HIST_BLOCKS + mlp_blocks, 256, SMEM_FLOATS * 4>>>(
        x, W1, W2, a, dst, N, E);

    scan_kernel<<<1, 1024>>>(N);
    scatter_kernel<<<(E + 255) / 256, 256>>>(src, dst, E);
    aggregate_kernel<<<(N * 32 + 255) / 256, 256>>>(out, N);
}